// round 5
// baseline (speedup 1.0000x reference)
#include <cuda_runtime.h>
#include <cstddef>

// LSTM_824633721296: 2-layer LSTM (B=1024, T=512, I=8, H=64) + FC (O=10)
// 128 blocks x 256 threads (8 warps, 2/SMSP). K-SPLIT design:
//   warps 0-3 (kh=0): first K-half,  partial gates -> gA
//   warps 4-7 (kh=1): second K-half, partial gates -> gB
// Thread = 2 gate rows (ht, ht+128) x all 8 batches x K/2.
// Weights read ONCE per block-step (32-distinct-granule LDS.128 = 4 wf = 128B/wf),
// A operands warp-uniform (1 wf). Elem phase fuses gA+gB+bias reduction.
// h/x buffers single-buffered in place (syncs make it safe). tanh.approx acts.

#define BT        8
#define NB        128
#define NTHREADS  256
#define HID       64
#define TSTEPS    512
#define IDIM      8
#define ODIM      10

#define W0_STRIDE 68      // h-part only (64 cols) + 4 pad; 17 f4 (odd) -> conflict-free
#define W1_STRIDE 132     // 128 cols + 4 pad; 33 f4 (odd)
#define GSTR      256     // warp-constant batch in every access -> no padding needed
#define HSTR      64
#define XSTR      8

// smem layout (floats)
#define OFF_W0    0
#define OFF_W1    (OFF_W0 + 256*W0_STRIDE)        // 17408
#define OFF_GA    (OFF_W1 + 256*W1_STRIDE)        // 51200
#define OFF_GB    (OFF_GA + BT*GSTR)              // 53248
#define OFF_H0    (OFF_GB + BT*GSTR)              // 55296
#define OFF_H1    (OFF_H0 + BT*HSTR)              // 55808
#define OFF_XS    (OFF_H1 + BT*HSTR)              // 56320
#define SMEM_FLOATS (OFF_XS + BT*XSTR)            // 56384 floats = 225536 B

__device__ __forceinline__ float tanha(float x) {
    float r;
    asm("tanh.approx.f32 %0, %1;" : "=f"(r) : "f"(x));
    return r;
}
__device__ __forceinline__ float sigm_(float x) {
    // sigmoid(x) = 0.5*tanh(0.5x) + 0.5
    return fmaf(0.5f, tanha(0.5f * x), 0.5f);
}

__device__ __forceinline__ void ffma2(unsigned long long& acc,
                                      unsigned long long a,
                                      unsigned long long w) {
    asm("fma.rn.f32x2 %0, %1, %2, %0;" : "+l"(acc) : "l"(a), "l"(w));
}
__device__ __forceinline__ float hsum2(unsigned long long v) {
    float lo, hi;
    asm("mov.b64 {%0, %1}, %2;" : "=f"(lo), "=f"(hi) : "l"(v));
    return lo + hi;
}

extern __shared__ float smem[];

__global__ void __launch_bounds__(NTHREADS, 1)
lstm_persistent_kernel(const float* __restrict__ x,
                       const float* __restrict__ w_ih0, const float* __restrict__ w_hh0,
                       const float* __restrict__ b_ih0, const float* __restrict__ b_hh0,
                       const float* __restrict__ w_ih1, const float* __restrict__ w_hh1,
                       const float* __restrict__ b_ih1, const float* __restrict__ b_hh1,
                       const float* __restrict__ w_fc,  const float* __restrict__ b_fc,
                       float* __restrict__ out)
{
    float* W0  = smem + OFF_W0;   // [256][68]  cols 0..63 = w_hh0 (x-weights live in regs)
    float* W1  = smem + OFF_W1;   // [256][132] cols 0..63 = w_ih1, 64..127 = w_hh1
    float* gA  = smem + OFF_GA;   // [8][256] partial gates, K-half 0
    float* gB  = smem + OFF_GB;   // [8][256] partial gates, K-half 1
    float* h0s = smem + OFF_H0;   // [8][64] in-place
    float* h1s = smem + OFF_H1;   // [8][64] in-place
    float* xs  = smem + OFF_XS;   // [8][8]  in-place

    const int tid = threadIdx.x;
    const int b0  = blockIdx.x * BT;

    // ---- stage weights into SMEM ----
    for (int i = tid; i < 256 * 64; i += NTHREADS) W0[(i >> 6) * W0_STRIDE + (i & 63)]      = w_hh0[i];
    for (int i = tid; i < 256 * 64; i += NTHREADS) W1[(i >> 6) * W1_STRIDE + (i & 63)]      = w_ih1[i];
    for (int i = tid; i < 256 * 64; i += NTHREADS) W1[(i >> 6) * W1_STRIDE + 64 + (i & 63)] = w_hh1[i];
    for (int i = tid; i < BT * HSTR; i += NTHREADS) { h0s[i] = 0.0f; h1s[i] = 0.0f; }

    // x(t=0)
    if (tid < 16) {
        int b = tid >> 1, q = tid & 1;
        float4 v = *(const float4*)(x + (size_t)(b0 + b) * TSTEPS * IDIM + q * 4);
        *(float4*)(xs + b * XSTR + q * 4) = v;
    }

    // ---- GEMM mapping ----
    const int kh = tid >> 7;          // K-half (warps 0-3 / 4-7)
    const int ht = tid & 127;
    const int r0 = ht, r1 = ht + 128; // this thread's 2 gate rows

    // x-part weights of layer 0 in registers (kh=0 threads only)
    unsigned long long wx0[4], wx1[4];
    if (kh == 0) {
        ulonglong2 t0 = ((const ulonglong2*)(w_ih0 + r0 * IDIM))[0];
        ulonglong2 t1 = ((const ulonglong2*)(w_ih0 + r0 * IDIM))[1];
        wx0[0] = t0.x; wx0[1] = t0.y; wx0[2] = t1.x; wx0[3] = t1.y;
        ulonglong2 u0 = ((const ulonglong2*)(w_ih0 + r1 * IDIM))[0];
        ulonglong2 u1 = ((const ulonglong2*)(w_ih0 + r1 * IDIM))[1];
        wx1[0] = u0.x; wx1[1] = u0.y; wx1[2] = u1.x; wx1[3] = u1.y;
    }

    // ---- elem mapping: warp = 1 batch; thread = 2 h-elements ----
    const int eb  = tid >> 5;         // 0..7
    const int ehb = tid & 31;
    float ebias0[2][4], ebias1[2][4];
    #pragma unroll
    for (int j = 0; j < 2; j++) {
        int h = ehb + 32 * j;
        #pragma unroll
        for (int g = 0; g < 4; g++) {
            ebias0[j][g] = b_ih0[h + 64 * g] + b_hh0[h + 64 * g];
            ebias1[j][g] = b_ih1[h + 64 * g] + b_hh1[h + 64 * g];
        }
    }
    float c0[2] = {0.f, 0.f}, c1[2] = {0.f, 0.f};

    __syncthreads();

    const ulonglong2* w0r0 = (const ulonglong2*)(W0 + r0 * W0_STRIDE);
    const ulonglong2* w0r1 = (const ulonglong2*)(W0 + r1 * W0_STRIDE);
    const ulonglong2* w1r0 = (const ulonglong2*)(W1 + r0 * W1_STRIDE) + kh * 16;
    const ulonglong2* w1r1 = (const ulonglong2*)(W1 + r1 * W1_STRIDE) + kh * 16;
    float* pg = kh ? gB : gA;         // this half's partial buffer
    // GEMM1 A operand: kh0 -> h0_new (w_ih1 cols), kh1 -> h1_old (w_hh1 cols)
    const ulonglong2* g1hq = (const ulonglong2*)(kh ? h1s : h0s);

    for (int t = 0; t < TSTEPS; t++) {
        // prefetch x(t+1) (global; latency hidden behind GEMM0)
        float4 xpre = make_float4(0.f, 0.f, 0.f, 0.f);
        const bool doPre = (tid < 16) && (t + 1 < TSTEPS);
        if (doPre) {
            int b = tid >> 1, q = tid & 1;
            xpre = *(const float4*)(x + (size_t)(b0 + b) * TSTEPS * IDIM + (size_t)(t + 1) * IDIM + q * 4);
        }

        unsigned long long accA[8], accB[8];

        // ========== GEMM 0 partials: [x | h0] @ W0^T (K split) ==========
        #pragma unroll
        for (int b = 0; b < 8; b++) { accA[b] = 0ull; accB[b] = 0ull; }
        if (kh == 0) {
            // x part (K=8, weights in regs) + h f4 0..6
            const ulonglong2* xq = (const ulonglong2*)xs;
            #pragma unroll
            for (int b = 0; b < 8; b++) {
                ulonglong2 a1 = xq[b * 2];
                ulonglong2 a2 = xq[b * 2 + 1];
                ffma2(accA[b], a1.x, wx0[0]); ffma2(accA[b], a1.y, wx0[1]);
                ffma2(accA[b], a2.x, wx0[2]); ffma2(accA[b], a2.y, wx0[3]);
                ffma2(accB[b], a1.x, wx1[0]); ffma2(accB[b], a1.y, wx1[1]);
                ffma2(accB[b], a2.x, wx1[2]); ffma2(accB[b], a2.y, wx1[3]);
            }
            const ulonglong2* hq = (const ulonglong2*)h0s;
            #pragma unroll
            for (int q = 0; q < 7; q++) {
                ulonglong2 wA = w0r0[q];
                ulonglong2 wB = w0r1[q];
                #pragma unroll
                for (int b = 0; b < 8; b++) {
                    ulonglong2 av = hq[b * 16 + q];
                    ffma2(accA[b], av.x, wA.x); ffma2(accA[b], av.y, wA.y);
                    ffma2(accB[b], av.x, wB.x); ffma2(accB[b], av.y, wB.y);
                }
            }
        } else {
            // h f4 7..15
            const ulonglong2* hq = (const ulonglong2*)h0s;
            #pragma unroll
            for (int q = 7; q < 16; q++) {
                ulonglong2 wA = w0r0[q];
                ulonglong2 wB = w0r1[q];
                #pragma unroll
                for (int b = 0; b < 8; b++) {
                    ulonglong2 av = hq[b * 16 + q];
                    ffma2(accA[b], av.x, wA.x); ffma2(accA[b], av.y, wA.y);
                    ffma2(accB[b], av.x, wB.x); ffma2(accB[b], av.y, wB.y);
                }
            }
        }
        #pragma unroll
        for (int b = 0; b < 8; b++) {
            pg[b * GSTR + r0] = hsum2(accA[b]);
            pg[b * GSTR + r1] = hsum2(accB[b]);
        }
        __syncthreads();

        // ========== ELEM 0: reduce gA+gB+bias, update c0, write h0 in place ==========
        {
            const float* ga = gA + eb * GSTR;
            const float* gb = gB + eb * GSTR;
            float* hd = h0s + eb * HSTR;
            #pragma unroll
            for (int j = 0; j < 2; j++) {
                int h = ehb + 32 * j;
                float gi = ga[h]       + gb[h]       + ebias0[j][0];
                float gf = ga[h + 64]  + gb[h + 64]  + ebias0[j][1];
                float gg = ga[h + 128] + gb[h + 128] + ebias0[j][2];
                float go = ga[h + 192] + gb[h + 192] + ebias0[j][3];
                float iv = sigm_(gi), fv = sigm_(gf), gv = tanha(gg), ov = sigm_(go);
                c0[j] = fv * c0[j] + iv * gv;
                hd[h] = ov * tanha(c0[j]);
            }
        }
        // store x(t+1) (xs consumed by GEMM0 before the sync above)
        if (doPre) {
            int b = tid >> 1, q = tid & 1;
            *(float4*)(xs + b * XSTR + q * 4) = xpre;
        }
        __syncthreads();

        // ========== GEMM 1 partials: kh0 = w_ih1 @ h0_new, kh1 = w_hh1 @ h1_old ==========
        #pragma unroll
        for (int b = 0; b < 8; b++) { accA[b] = 0ull; accB[b] = 0ull; }
        #pragma unroll
        for (int q = 0; q < 16; q++) {
            ulonglong2 wA = w1r0[q];
            ulonglong2 wB = w1r1[q];
            #pragma unroll
            for (int b = 0; b < 8; b++) {
                ulonglong2 av = g1hq[b * 16 + q];
                ffma2(accA[b], av.x, wA.x); ffma2(accA[b], av.y, wA.y);
                ffma2(accB[b], av.x, wB.x); ffma2(accB[b], av.y, wB.y);
            }
        }
        #pragma unroll
        for (int b = 0; b < 8; b++) {
            pg[b * GSTR + r0] = hsum2(accA[b]);
            pg[b * GSTR + r1] = hsum2(accB[b]);
        }
        __syncthreads();

        // ========== ELEM 1 ==========
        {
            const float* ga = gA + eb * GSTR;
            const float* gb = gB + eb * GSTR;
            float* hd = h1s + eb * HSTR;
            #pragma unroll
            for (int j = 0; j < 2; j++) {
                int h = ehb + 32 * j;
                float gi = ga[h]       + gb[h]       + ebias1[j][0];
                float gf = ga[h + 64]  + gb[h + 64]  + ebias1[j][1];
                float gg = ga[h + 128] + gb[h + 128] + ebias1[j][2];
                float go = ga[h + 192] + gb[h + 192] + ebias1[j][3];
                float iv = sigm_(gi), fv = sigm_(gf), gv = tanha(gg), ov = sigm_(go);
                c1[j] = fv * c1[j] + iv * gv;
                hd[h] = ov * tanha(c1[j]);
            }
        }
        __syncthreads();
    }

    // ========== FC: out = h1_final @ w_fc^T + b_fc ==========
    if (tid < BT * ODIM) {
        int b = tid / ODIM, o = tid % ODIM;
        const float* hrow = h1s + b * HSTR;
        const float* wrow = w_fc + o * HID;
        float s = b_fc[o];
        #pragma unroll 16
        for (int k = 0; k < HID; k++) s = fmaf(hrow[k], wrow[k], s);
        out[(size_t)(b0 + b) * ODIM + o] = s;
    }
}

extern "C" void kernel_launch(void* const* d_in, const int* in_sizes, int n_in,
                              void* d_out, int out_size)
{
    (void)in_sizes; (void)n_in; (void)out_size;
    const float* x     = (const float*)d_in[0];
    const float* w_ih0 = (const float*)d_in[1];
    const float* w_hh0 = (const float*)d_in[2];
    const float* b_ih0 = (const float*)d_in[3];
    const float* b_hh0 = (const float*)d_in[4];
    const float* w_ih1 = (const float*)d_in[5];
    const float* w_hh1 = (const float*)d_in[6];
    const float* b_ih1 = (const float*)d_in[7];
    const float* b_hh1 = (const float*)d_in[8];
    const float* w_fc  = (const float*)d_in[9];
    const float* b_fc  = (const float*)d_in[10];

    const size_t smem_bytes = (size_t)SMEM_FLOATS * sizeof(float);
    cudaFuncSetAttribute(lstm_persistent_kernel,
                         cudaFuncAttributeMaxDynamicSharedMemorySize, (int)smem_bytes);
    lstm_persistent_kernel<<<NB, NTHREADS, smem_bytes>>>(
        x, w_ih0, w_hh0, b_ih0, b_hh0, w_ih1, w_hh1, b_ih1, b_hh1, w_fc, b_fc,
        (float*)d_out);
}

// round 6
// speedup vs baseline: 1.7357x; 1.7357x over previous
#include <cuda_runtime.h>
#include <cstddef>

// LSTM_824633721296: 2-layer LSTM (B=1024, T=512, I=8, H=64) + FC (O=10)
// 128 blocks x 512 threads (16 warps, 4/SMSP). K-SPLIT x2:
//   kh0 (warps 0-7):  GEMM0 x-part (regs) + h[0:32];  GEMM1 w_ih1 @ h0_new -> gA
//   kh1 (warps 8-15): GEMM0 h[32:64];                 GEMM1 w_hh1 @ h1_old -> gB
// Thread = 2 gate rows x 4 batches x K/2 -> 8 ull accumulators (lean regs).
// Elem phase fuses gA+gB+bias; 1 element/layer/thread. tanh.approx activations.

#define BT        8
#define NB        128
#define NTHREADS  512
#define HID       64
#define TSTEPS    512
#define IDIM      8
#define ODIM      10

#define W0_STRIDE 68      // h-part only (64 cols)+4 pad; 17 f4 (odd) -> conflict-free
#define W1_STRIDE 132     // 128 cols + 4 pad; 33 f4 (odd)
#define GSTR      256
#define HSTR      64
#define XSTR      8

// smem layout (floats)
#define OFF_W0    0
#define OFF_W1    (OFF_W0 + 256*W0_STRIDE)        // 17408
#define OFF_GA    (OFF_W1 + 256*W1_STRIDE)        // 51200
#define OFF_GB    (OFF_GA + BT*GSTR)              // 53248
#define OFF_H0    (OFF_GB + BT*GSTR)              // 55296
#define OFF_H1    (OFF_H0 + BT*HSTR)              // 55808
#define OFF_XS    (OFF_H1 + BT*HSTR)              // 56320
#define SMEM_FLOATS (OFF_XS + BT*XSTR)            // 56384 floats = 225536 B

__device__ __forceinline__ float tanha(float x) {
    float r;
    asm("tanh.approx.f32 %0, %1;" : "=f"(r) : "f"(x));
    return r;
}
__device__ __forceinline__ float sigm_(float x) {
    return fmaf(0.5f, tanha(0.5f * x), 0.5f);   // sigmoid via tanh
}

__device__ __forceinline__ void ffma2(unsigned long long& acc,
                                      unsigned long long a,
                                      unsigned long long w) {
    asm("fma.rn.f32x2 %0, %1, %2, %0;" : "+l"(acc) : "l"(a), "l"(w));
}
__device__ __forceinline__ float hsum2(unsigned long long v) {
    float lo, hi;
    asm("mov.b64 {%0, %1}, %2;" : "=f"(lo), "=f"(hi) : "l"(v));
    return lo + hi;
}

extern __shared__ float smem[];

__global__ void __launch_bounds__(NTHREADS, 1)
lstm_persistent_kernel(const float* __restrict__ x,
                       const float* __restrict__ w_ih0, const float* __restrict__ w_hh0,
                       const float* __restrict__ b_ih0, const float* __restrict__ b_hh0,
                       const float* __restrict__ w_ih1, const float* __restrict__ w_hh1,
                       const float* __restrict__ b_ih1, const float* __restrict__ b_hh1,
                       const float* __restrict__ w_fc,  const float* __restrict__ b_fc,
                       float* __restrict__ out)
{
    float* W0  = smem + OFF_W0;   // [256][68]  cols 0..63 = w_hh0 (x-weights in regs)
    float* W1  = smem + OFF_W1;   // [256][132] cols 0..63 = w_ih1, 64..127 = w_hh1
    float* gA  = smem + OFF_GA;   // [8][256] partial gates, kh0
    float* gB  = smem + OFF_GB;   // [8][256] partial gates, kh1
    float* h0s = smem + OFF_H0;   // [8][64] in place
    float* h1s = smem + OFF_H1;   // [8][64] in place
    float* xs  = smem + OFF_XS;   // [8][8]  in place

    const int tid = threadIdx.x;
    const int b0  = blockIdx.x * BT;

    // ---- stage weights ----
    for (int i = tid; i < 256 * 64; i += NTHREADS) W0[(i >> 6) * W0_STRIDE + (i & 63)]      = w_hh0[i];
    for (int i = tid; i < 256 * 64; i += NTHREADS) W1[(i >> 6) * W1_STRIDE + (i & 63)]      = w_ih1[i];
    for (int i = tid; i < 256 * 64; i += NTHREADS) W1[(i >> 6) * W1_STRIDE + 64 + (i & 63)] = w_hh1[i];
    for (int i = tid; i < BT * HSTR; i += NTHREADS) { h0s[i] = 0.0f; h1s[i] = 0.0f; }

    // x(t=0)
    if (tid < 16) {
        int b = tid >> 1, q = tid & 1;
        float4 v = *(const float4*)(x + (size_t)(b0 + b) * TSTEPS * IDIM + q * 4);
        *(float4*)(xs + b * XSTR + q * 4) = v;
    }

    // ---- GEMM mapping: kh = K-half, bg = batch group, ht = row pair ----
    const int kh = tid >> 8;            // warps 0-7 vs 8-15
    const int bb = ((tid >> 7) & 1) * 4;
    const int ht = tid & 127;
    const int r0 = ht, r1 = ht + 128;

    // layer-0 x-part weights in regs (kh0 threads only): 8 floats per row
    unsigned long long wx0[4], wx1[4];
    if (kh == 0) {
        ulonglong2 t0 = ((const ulonglong2*)(w_ih0 + r0 * IDIM))[0];
        ulonglong2 t1 = ((const ulonglong2*)(w_ih0 + r0 * IDIM))[1];
        wx0[0] = t0.x; wx0[1] = t0.y; wx0[2] = t1.x; wx0[3] = t1.y;
        ulonglong2 u0 = ((const ulonglong2*)(w_ih0 + r1 * IDIM))[0];
        ulonglong2 u1 = ((const ulonglong2*)(w_ih0 + r1 * IDIM))[1];
        wx1[0] = u0.x; wx1[1] = u0.y; wx1[2] = u1.x; wx1[3] = u1.y;
    }

    // ---- elem mapping: 1 element per layer per thread ----
    const int eb = tid >> 6;            // 0..7
    const int eh = tid & 63;
    float ebias0[4], ebias1[4];
    #pragma unroll
    for (int g = 0; g < 4; g++) {
        ebias0[g] = b_ih0[eh + 64 * g] + b_hh0[eh + 64 * g];
        ebias1[g] = b_ih1[eh + 64 * g] + b_hh1[eh + 64 * g];
    }
    float c0 = 0.0f, c1 = 0.0f;

    __syncthreads();

    const ulonglong2* w0r0 = (const ulonglong2*)(W0 + r0 * W0_STRIDE) + kh * 8;
    const ulonglong2* w0r1 = (const ulonglong2*)(W0 + r1 * W0_STRIDE) + kh * 8;
    const ulonglong2* w1r0 = (const ulonglong2*)(W1 + r0 * W1_STRIDE) + kh * 16;
    const ulonglong2* w1r1 = (const ulonglong2*)(W1 + r1 * W1_STRIDE) + kh * 16;
    float* pg = kh ? gB : gA;
    const ulonglong2* g1aq = (const ulonglong2*)(kh ? h1s : h0s);  // GEMM1 A operand

    for (int t = 0; t < TSTEPS; t++) {
        // prefetch x(t+1)
        float4 xpre = make_float4(0.f, 0.f, 0.f, 0.f);
        const bool doPre = (tid < 16) && (t + 1 < TSTEPS);
        if (doPre) {
            int b = tid >> 1, q = tid & 1;
            xpre = *(const float4*)(x + (size_t)(b0 + b) * TSTEPS * IDIM + (size_t)(t + 1) * IDIM + q * 4);
        }

        unsigned long long accA[4], accB[4];

        // ========== GEMM 0 partials ==========
        #pragma unroll
        for (int b = 0; b < 4; b++) { accA[b] = 0ull; accB[b] = 0ull; }
        {
            const ulonglong2* hq = (const ulonglong2*)h0s;
            if (kh == 0) {
                const ulonglong2* xq = (const ulonglong2*)xs;
                #pragma unroll
                for (int b = 0; b < 4; b++) {
                    ulonglong2 a1 = xq[(bb + b) * 2];
                    ulonglong2 a2 = xq[(bb + b) * 2 + 1];
                    ffma2(accA[b], a1.x, wx0[0]); ffma2(accA[b], a1.y, wx0[1]);
                    ffma2(accA[b], a2.x, wx0[2]); ffma2(accA[b], a2.y, wx0[3]);
                    ffma2(accB[b], a1.x, wx1[0]); ffma2(accB[b], a1.y, wx1[1]);
                    ffma2(accB[b], a2.x, wx1[2]); ffma2(accB[b], a2.y, wx1[3]);
                }
                #pragma unroll
                for (int q = 0; q < 8; q++) {          // h cols 0..31
                    ulonglong2 wA = w0r0[q];
                    ulonglong2 wB = w0r1[q];
                    #pragma unroll
                    for (int b = 0; b < 4; b++) {
                        ulonglong2 av = hq[(bb + b) * 16 + q];   // warp-uniform
                        ffma2(accA[b], av.x, wA.x); ffma2(accA[b], av.y, wA.y);
                        ffma2(accB[b], av.x, wB.x); ffma2(accB[b], av.y, wB.y);
                    }
                }
            } else {
                #pragma unroll
                for (int q = 0; q < 8; q++) {          // h cols 32..63 (ptr pre-offset)
                    ulonglong2 wA = w0r0[q];
                    ulonglong2 wB = w0r1[q];
                    #pragma unroll
                    for (int b = 0; b < 4; b++) {
                        ulonglong2 av = hq[(bb + b) * 16 + 8 + q];
                        ffma2(accA[b], av.x, wA.x); ffma2(accA[b], av.y, wA.y);
                        ffma2(accB[b], av.x, wB.x); ffma2(accB[b], av.y, wB.y);
                    }
                }
            }
        }
        #pragma unroll
        for (int b = 0; b < 4; b++) {
            pg[(bb + b) * GSTR + r0] = hsum2(accA[b]);
            pg[(bb + b) * GSTR + r1] = hsum2(accB[b]);
        }
        __syncthreads();

        // ========== ELEM 0: gA+gB+bias, c0 update, h0 in place ==========
        {
            const float* ga = gA + eb * GSTR + eh;
            const float* gb = gB + eb * GSTR + eh;
            float gi = ga[0]   + gb[0]   + ebias0[0];
            float gf = ga[64]  + gb[64]  + ebias0[1];
            float gg = ga[128] + gb[128] + ebias0[2];
            float go = ga[192] + gb[192] + ebias0[3];
            float iv = sigm_(gi), fv = sigm_(gf), gv = tanha(gg), ov = sigm_(go);
            c0 = fv * c0 + iv * gv;
            h0s[eb * HSTR + eh] = ov * tanha(c0);
        }
        if (doPre) {
            int b = tid >> 1, q = tid & 1;
            *(float4*)(xs + b * XSTR + q * 4) = xpre;
        }
        __syncthreads();

        // ========== GEMM 1 partials: kh0 = w_ih1 @ h0_new, kh1 = w_hh1 @ h1_old ==========
        #pragma unroll
        for (int b = 0; b < 4; b++) { accA[b] = 0ull; accB[b] = 0ull; }
        #pragma unroll
        for (int q = 0; q < 16; q++) {
            ulonglong2 wA = w1r0[q];
            ulonglong2 wB = w1r1[q];
            #pragma unroll
            for (int b = 0; b < 4; b++) {
                ulonglong2 av = g1aq[(bb + b) * 16 + q];   // warp-uniform
                ffma2(accA[b], av.x, wA.x); ffma2(accA[b], av.y, wA.y);
                ffma2(accB[b], av.x, wB.x); ffma2(accB[b], av.y, wB.y);
            }
        }
        #pragma unroll
        for (int b = 0; b < 4; b++) {
            pg[(bb + b) * GSTR + r0] = hsum2(accA[b]);
            pg[(bb + b) * GSTR + r1] = hsum2(accB[b]);
        }
        __syncthreads();

        // ========== ELEM 1 ==========
        {
            const float* ga = gA + eb * GSTR + eh;
            const float* gb = gB + eb * GSTR + eh;
            float gi = ga[0]   + gb[0]   + ebias1[0];
            float gf = ga[64]  + gb[64]  + ebias1[1];
            float gg = ga[128] + gb[128] + ebias1[2];
            float go = ga[192] + gb[192] + ebias1[3];
            float iv = sigm_(gi), fv = sigm_(gf), gv = tanha(gg), ov = sigm_(go);
            c1 = fv * c1 + iv * gv;
            h1s[eb * HSTR + eh] = ov * tanha(c1);
        }
        __syncthreads();
    }

    // ========== FC ==========
    if (tid < BT * ODIM) {
        int b = tid / ODIM, o = tid % ODIM;
        const float* hrow = h1s + b * HSTR;
        const float* wrow = w_fc + o * HID;
        float s = b_fc[o];
        #pragma unroll 16
        for (int k = 0; k < HID; k++) s = fmaf(hrow[k], wrow[k], s);
        out[(size_t)(b0 + b) * ODIM + o] = s;
    }
}

extern "C" void kernel_launch(void* const* d_in, const int* in_sizes, int n_in,
                              void* d_out, int out_size)
{
    (void)in_sizes; (void)n_in; (void)out_size;
    const float* x     = (const float*)d_in[0];
    const float* w_ih0 = (const float*)d_in[1];
    const float* w_hh0 = (const float*)d_in[2];
    const float* b_ih0 = (const float*)d_in[3];
    const float* b_hh0 = (const float*)d_in[4];
    const float* w_ih1 = (const float*)d_in[5];
    const float* w_hh1 = (const float*)d_in[6];
    const float* b_ih1 = (const float*)d_in[7];
    const float* b_hh1 = (const float*)d_in[8];
    const float* w_fc  = (const float*)d_in[9];
    const float* b_fc  = (const float*)d_in[10];

    const size_t smem_bytes = (size_t)SMEM_FLOATS * sizeof(float);
    cudaFuncSetAttribute(lstm_persistent_kernel,
                         cudaFuncAttributeMaxDynamicSharedMemorySize, (int)smem_bytes);
    lstm_persistent_kernel<<<NB, NTHREADS, smem_bytes>>>(
        x, w_ih0, w_hh0, b_ih0, b_hh0, w_ih1, w_hh1, b_ih1, b_hh1, w_fc, b_fc,
        (float*)d_out);
}

// round 9
// speedup vs baseline: 3.2981x; 1.9001x over previous
#include <cuda_runtime.h>
#include <cuda_bf16.h>
#include <cstdint>
#include <cstddef>

// LSTM_824633721296: 2-layer LSTM (B=1024, T=512, I=8, H=64) + FC (O=10)
// Warp-level tensor core design (plain sm_100-compatible): mma.sync.m16n8k16
// bf16 hi/lo 3-term with fp32 accumulators; ldmatrix A-frags from resident
// smem weights; B-frags composed via conflict-free LDS.32.
// 128 blocks x 256 threads (8 warps). x-part exact fp32; tanh.approx acts.

#define BT       8
#define NB       128
#define NTHREADS 256
#define HID      64
#define TSTEPS   512
#define IDIM     8
#define ODIM     10

#define GSTR 260            // gate buffer stride (floats)
#define W0S  144            // W0 row stride bytes (64 bf16 + pad) - 9 granules, odd
#define W1S  256            // W1 row stride bytes (128 bf16, XOR-swizzled)
#define B0S  144            // B0 row stride bytes (64 bf16 + pad)
#define B1S  272            // B1 row stride bytes (128 bf16 + pad) - 17 granules, odd

// smem byte offsets
#define SM_W0H 0            // [256][144]
#define SM_W0L 36864
#define SM_W1H 73728        // [256][256] swizzled
#define SM_W1L 139264
#define SM_B0H 204800       // [8][144]  h0 (layer-0 B operand)
#define SM_B0L 205952
#define SM_B1H 207104       // [8][272]  [h0new | h1old] (layer-1 B operand)
#define SM_B1L 209280
#define SM_G0  211456       // f32 [8][260]
#define SM_G1  219776       // f32 [8][260]
#define SM_XS  228096       // f32 [8][8]
#define SM_H1F 228352       // f32 [8][64]
#define SMEM_BYTES 230400

__device__ __forceinline__ void ldmx4(uint32_t r[4], uint32_t addr) {
    asm volatile("ldmatrix.sync.aligned.m8n8.x4.shared.b16 {%0,%1,%2,%3}, [%4];"
                 : "=r"(r[0]), "=r"(r[1]), "=r"(r[2]), "=r"(r[3]) : "r"(addr));
}
__device__ __forceinline__ void mma16816(float d[4], const uint32_t a[4],
                                         uint32_t b0, uint32_t b1) {
    asm volatile("mma.sync.aligned.m16n8k16.row.col.f32.bf16.bf16.f32 "
                 "{%0,%1,%2,%3}, {%4,%5,%6,%7}, {%8,%9}, {%0,%1,%2,%3};"
                 : "+f"(d[0]), "+f"(d[1]), "+f"(d[2]), "+f"(d[3])
                 : "r"(a[0]), "r"(a[1]), "r"(a[2]), "r"(a[3]), "r"(b0), "r"(b1));
}
__device__ __forceinline__ float tanha(float x) {
    float r; asm("tanh.approx.f32 %0, %1;" : "=f"(r) : "f"(x)); return r;
}
__device__ __forceinline__ float sigm_(float x) {
    return fmaf(0.5f, tanha(0.5f * x), 0.5f);
}
__device__ __forceinline__ void split_bf16(float v, __nv_bfloat16& hi, __nv_bfloat16& lo) {
    hi = __float2bfloat16(v);
    lo = __float2bfloat16(v - __bfloat162float(hi));
}
__device__ __forceinline__ void ffma2(unsigned long long& acc,
                                      unsigned long long a,
                                      unsigned long long w) {
    asm("fma.rn.f32x2 %0, %1, %2, %0;" : "+l"(acc) : "l"(a), "l"(w));
}
__device__ __forceinline__ float hsum2(unsigned long long v) {
    float lo, hi;
    asm("mov.b64 {%0, %1}, %2;" : "=f"(lo), "=f"(hi) : "l"(v));
    return lo + hi;
}

extern __shared__ char smem[];

__global__ void __launch_bounds__(NTHREADS, 1)
lstm_wmma_kernel(const float* __restrict__ x,
                 const float* __restrict__ w_ih0, const float* __restrict__ w_hh0,
                 const float* __restrict__ b_ih0, const float* __restrict__ b_hh0,
                 const float* __restrict__ w_ih1, const float* __restrict__ w_hh1,
                 const float* __restrict__ b_ih1, const float* __restrict__ b_hh1,
                 const float* __restrict__ w_fc,  const float* __restrict__ b_fc,
                 float* __restrict__ out)
{
    const int tid  = threadIdx.x;
    const int w    = tid >> 5;
    const int lane = tid & 31;
    const int b0   = blockIdx.x * BT;

    uint32_t smb;
    asm("{ .reg .u64 t; cvta.to.shared.u64 t, %1; cvt.u32.u64 %0, t; }"
        : "=r"(smb) : "l"(smem));

    // ---- zero B operand buffers (h state starts at 0; pads must be 0) ----
    for (int i = tid; i < (8 * B0S) / 4; i += NTHREADS) {
        ((uint32_t*)(smem + SM_B0H))[i] = 0;
        ((uint32_t*)(smem + SM_B0L))[i] = 0;
    }
    for (int i = tid; i < (8 * B1S) / 4; i += NTHREADS) {
        ((uint32_t*)(smem + SM_B1H))[i] = 0;
        ((uint32_t*)(smem + SM_B1L))[i] = 0;
    }

    // ---- stage weights as bf16 hi/lo ----
    // W0 = w_hh0 [256 x 64], row stride 144B (no swizzle; 9 granules odd)
    for (int i = tid; i < 256 * 64; i += NTHREADS) {
        int r = i >> 6, k = i & 63;
        __nv_bfloat16 hi, lo; split_bf16(w_hh0[i], hi, lo);
        uint32_t a = r * W0S + k * 2;
        *(__nv_bfloat16*)(smem + SM_W0H + a) = hi;
        *(__nv_bfloat16*)(smem + SM_W0L + a) = lo;
    }
    // W1 = [w_ih1 | w_hh1] [256 x 128], row stride 256B, XOR-16B swizzle by row
    for (int i = tid; i < 256 * 128; i += NTHREADS) {
        int r = i >> 7, k = i & 127;
        float v = (k < 64) ? w_ih1[r * 64 + k] : w_hh1[r * 64 + (k - 64)];
        __nv_bfloat16 hi, lo; split_bf16(v, hi, lo);
        uint32_t off = (uint32_t)(k * 2) ^ (uint32_t)((r & 7) << 4);
        uint32_t a = r * W1S + off;
        *(__nv_bfloat16*)(smem + SM_W1H + a) = hi;
        *(__nv_bfloat16*)(smem + SM_W1L + a) = lo;
    }

    // ---- per-thread row constants (row = tid, 256 rows exactly) ----
    const float bias0r = b_ih0[tid] + b_hh0[tid];
    const float bias1r = b_ih1[tid] + b_hh1[tid];
    unsigned long long wx[4];
    {
        ulonglong2 t0 = ((const ulonglong2*)(w_ih0 + tid * IDIM))[0];
        ulonglong2 t1 = ((const ulonglong2*)(w_ih0 + tid * IDIM))[1];
        wx[0] = t0.x; wx[1] = t0.y; wx[2] = t1.x; wx[3] = t1.y;
    }

    float* g0f = (float*)(smem + SM_G0);
    float* g1f = (float*)(smem + SM_G1);
    float* xsf = (float*)(smem + SM_XS);
    float* h1f = (float*)(smem + SM_H1F);

    // ---- prologue: gates0 prestore for t=0: xg(x(0)) + bias0 ----
    #pragma unroll
    for (int b = 0; b < 8; b++) {
        ulonglong2 a1 = ((const ulonglong2*)(x + (size_t)(b0 + b) * TSTEPS * IDIM))[0];
        ulonglong2 a2 = ((const ulonglong2*)(x + (size_t)(b0 + b) * TSTEPS * IDIM))[1];
        unsigned long long s = 0ull;
        ffma2(s, a1.x, wx[0]); ffma2(s, a1.y, wx[1]);
        ffma2(s, a2.x, wx[2]); ffma2(s, a2.y, wx[3]);
        g0f[b * GSTR + tid] = hsum2(s) + bias0r;
    }

    // mma lane geometry
    const int aRow  = lane & 15;        // ldmatrix source row within m-tile
    const int aHalf = lane >> 4;        // k-half (0/1) of 16-wide k-tile
    const int bn    = lane >> 2;        // B-frag batch (n)
    const int bq    = lane & 3;         // B-frag k-quad
    const int dq    = lane & 3, dg = lane >> 2;   // D-frag coords

    // elem geometry: warp = batch
    const int eb = w;
    float c0[2] = {0.f, 0.f}, c1[2] = {0.f, 0.f};

    __syncthreads();

    for (int t = 0; t < TSTEPS; t++) {
        // ================= PHASE A: GEMM0  gates0 += W0 @ h0 =================
        {
            float d[2][4] = {{0.f,0.f,0.f,0.f},{0.f,0.f,0.f,0.f}};
            #pragma unroll
            for (int kt = 0; kt < 4; kt++) {
                uint32_t boff = bn * B0S + kt * 32 + bq * 4;
                uint32_t bh0 = *(const uint32_t*)(smem + SM_B0H + boff);
                uint32_t bh1 = *(const uint32_t*)(smem + SM_B0H + boff + 16);
                uint32_t bl0 = *(const uint32_t*)(smem + SM_B0L + boff);
                uint32_t bl1 = *(const uint32_t*)(smem + SM_B0L + boff + 16);
                #pragma unroll
                for (int mi = 0; mi < 2; mi++) {
                    int mb = 16 * (2 * w + mi);
                    uint32_t ro = (uint32_t)(mb + aRow) * W0S + kt * 32 + aHalf * 16;
                    uint32_t ah[4], al[4];
                    ldmx4(ah, smb + SM_W0H + ro);
                    ldmx4(al, smb + SM_W0L + ro);
                    mma16816(d[mi], ah, bh0, bh1);
                    mma16816(d[mi], ah, bl0, bl1);
                    mma16816(d[mi], al, bh0, bh1);
                }
            }
            #pragma unroll
            for (int mi = 0; mi < 2; mi++) {
                int mb = 16 * (2 * w + mi);
                g0f[(2*dq)   * GSTR + mb + dg]     += d[mi][0];
                g0f[(2*dq+1) * GSTR + mb + dg]     += d[mi][1];
                g0f[(2*dq)   * GSTR + mb + dg + 8] += d[mi][2];
                g0f[(2*dq+1) * GSTR + mb + dg + 8] += d[mi][3];
            }
        }
        __syncthreads();

        // ================= PHASE B: elem0 + bias1 prestore =================
        {
            const float* g = g0f + eb * GSTR;
            #pragma unroll
            for (int j = 0; j < 2; j++) {
                int h = lane + 32 * j;
                float iv = sigm_(g[h]);
                float fv = sigm_(g[h + 64]);
                float gv = tanha(g[h + 128]);
                float ov = sigm_(g[h + 192]);
                c0[j] = fv * c0[j] + iv * gv;
                float hv = ov * tanha(c0[j]);
                __nv_bfloat16 hi, lo; split_bf16(hv, hi, lo);
                *(__nv_bfloat16*)(smem + SM_B0H + eb * B0S + h * 2) = hi;  // next-step GEMM0
                *(__nv_bfloat16*)(smem + SM_B0L + eb * B0S + h * 2) = lo;
                *(__nv_bfloat16*)(smem + SM_B1H + eb * B1S + h * 2) = hi;  // this-step GEMM1
                *(__nv_bfloat16*)(smem + SM_B1L + eb * B1S + h * 2) = lo;
            }
            #pragma unroll
            for (int b = 0; b < 8; b++) g1f[b * GSTR + tid] = bias1r;
        }
        __syncthreads();

        // ================= PHASE C: GEMM1  gates1 += W1 @ [h0new|h1old] =================
        // (also: prefetch x(t+1) into xs; global latency hidden behind mma)
        if (tid < 16 && t + 1 < TSTEPS) {
            int b = tid >> 1, qq = tid & 1;
            float4 v = *(const float4*)(x + (size_t)(b0 + b) * TSTEPS * IDIM
                                          + (size_t)(t + 1) * IDIM + qq * 4);
            *(float4*)(xsf + b * 8 + qq * 4) = v;
        }
        {
            float d[2][4] = {{0.f,0.f,0.f,0.f},{0.f,0.f,0.f,0.f}};
            #pragma unroll
            for (int kt = 0; kt < 8; kt++) {
                uint32_t boff = bn * B1S + kt * 32 + bq * 4;
                uint32_t bh0 = *(const uint32_t*)(smem + SM_B1H + boff);
                uint32_t bh1 = *(const uint32_t*)(smem + SM_B1H + boff + 16);
                uint32_t bl0 = *(const uint32_t*)(smem + SM_B1L + boff);
                uint32_t bl1 = *(const uint32_t*)(smem + SM_B1L + boff + 16);
                #pragma unroll
                for (int mi = 0; mi < 2; mi++) {
                    int mb = 16 * (2 * w + mi);
                    int row = mb + aRow;
                    uint32_t off = (uint32_t)(kt * 32 + aHalf * 16)
                                 ^ (uint32_t)((row & 7) << 4);
                    uint32_t ro = (uint32_t)row * W1S + off;
                    uint32_t ah[4], al[4];
                    ldmx4(ah, smb + SM_W1H + ro);
                    ldmx4(al, smb + SM_W1L + ro);
                    mma16816(d[mi], ah, bh0, bh1);
                    mma16816(d[mi], ah, bl0, bl1);
                    mma16816(d[mi], al, bh0, bh1);
                }
            }
            #pragma unroll
            for (int mi = 0; mi < 2; mi++) {
                int mb = 16 * (2 * w + mi);
                g1f[(2*dq)   * GSTR + mb + dg]     += d[mi][0];
                g1f[(2*dq+1) * GSTR + mb + dg]     += d[mi][1];
                g1f[(2*dq)   * GSTR + mb + dg + 8] += d[mi][2];
                g1f[(2*dq+1) * GSTR + mb + dg + 8] += d[mi][3];
            }
        }
        __syncthreads();

        // ================= PHASE D: elem1 + xg(t+1)+bias0 prestore =================
        {
            const float* g = g1f + eb * GSTR;
            #pragma unroll
            for (int j = 0; j < 2; j++) {
                int h = lane + 32 * j;
                float iv = sigm_(g[h]);
                float fv = sigm_(g[h + 64]);
                float gv = tanha(g[h + 128]);
                float ov = sigm_(g[h + 192]);
                c1[j] = fv * c1[j] + iv * gv;
                float hv = ov * tanha(c1[j]);
                __nv_bfloat16 hi, lo; split_bf16(hv, hi, lo);
                *(__nv_bfloat16*)(smem + SM_B1H + eb * B1S + 128 + h * 2) = hi;
                *(__nv_bfloat16*)(smem + SM_B1L + eb * B1S + 128 + h * 2) = lo;
                if (t == TSTEPS - 1) h1f[eb * HID + h] = hv;
            }
            if (t + 1 < TSTEPS) {
                const ulonglong2* xq = (const ulonglong2*)xsf;
                #pragma unroll
                for (int b = 0; b < 8; b++) {
                    ulonglong2 a1 = xq[b * 2];
                    ulonglong2 a2 = xq[b * 2 + 1];
                    unsigned long long s = 0ull;
                    ffma2(s, a1.x, wx[0]); ffma2(s, a1.y, wx[1]);
                    ffma2(s, a2.x, wx[2]); ffma2(s, a2.y, wx[3]);
                    g0f[b * GSTR + tid] = hsum2(s) + bias0r;
                }
            }
        }
        __syncthreads();
    }

    // ================= FC: out = h1_final @ w_fc^T + b_fc =================
    if (tid < BT * ODIM) {
        int b = tid / ODIM, o = tid % ODIM;
        const float* hrow = h1f + b * HID;
        const float* wrow = w_fc + o * HID;
        float s = b_fc[o];
        #pragma unroll 16
        for (int k = 0; k < HID; k++) s = fmaf(hrow[k], wrow[k], s);
        out[(size_t)(b0 + b) * ODIM + o] = s;
    }
}

extern "C" void kernel_launch(void* const* d_in, const int* in_sizes, int n_in,
                              void* d_out, int out_size)
{
    (void)in_sizes; (void)n_in; (void)out_size;
    const float* x     = (const float*)d_in[0];
    const float* w_ih0 = (const float*)d_in[1];
    const float* w_hh0 = (const float*)d_in[2];
    const float* b_ih0 = (const float*)d_in[3];
    const float* b_hh0 = (const float*)d_in[4];
    const float* w_ih1 = (const float*)d_in[5];
    const float* w_hh1 = (const float*)d_in[6];
    const float* b_ih1 = (const float*)d_in[7];
    const float* b_hh1 = (const float*)d_in[8];
    const float* w_fc  = (const float*)d_in[9];
    const float* b_fc  = (const float*)d_in[10];

    cudaFuncSetAttribute(lstm_wmma_kernel,
                         cudaFuncAttributeMaxDynamicSharedMemorySize, SMEM_BYTES);
    lstm_wmma_kernel<<<NB, NTHREADS, SMEM_BYTES>>>(
        x, w_ih0, w_hh0, b_ih0, b_hh0, w_ih1, w_hh1, b_ih1, b_hh1, w_fc, b_fc,
        (float*)d_out);
}

// round 10
// speedup vs baseline: 3.4356x; 1.0417x over previous
#include <cuda_runtime.h>
#include <cuda_bf16.h>
#include <cstdint>
#include <cstddef>

// LSTM_824633721296: 2-layer LSTM (B=1024, T=512, I=8, H=64) + FC (O=10)
// Warp-level tensor cores (mma.sync.m16n8k16 bf16, fp32 accum), hi/lo 3-term.
// Round-10: W0 A-frags register-resident across all 512 steps; 3 independent
// accumulation chains per D-frag (HiHi/HiLo/LoHi) to break mma latency chains.
// 128 blocks x 256 threads. x-part exact fp32. tanh.approx activations.

#define BT       8
#define NB       128
#define NTHREADS 256
#define HID      64
#define TSTEPS   512
#define IDIM     8
#define ODIM     10

#define GSTR 260            // gate buffer stride (floats)
#define W0S  144            // W0 row stride bytes (64 bf16 + pad)
#define W1S  256            // W1 row stride bytes (128 bf16, XOR-swizzled)
#define B0S  144            // B0 row stride bytes
#define B1S  272            // B1 row stride bytes

// smem byte offsets
#define SM_W0H 0            // [256][144]
#define SM_W0L 36864
#define SM_W1H 73728        // [256][256] swizzled
#define SM_W1L 139264
#define SM_B0H 204800       // [8][144]  h0 (layer-0 B operand)
#define SM_B0L 205952
#define SM_B1H 207104       // [8][272]  [h0new | h1old] (layer-1 B operand)
#define SM_B1L 209280
#define SM_G0  211456       // f32 [8][260]
#define SM_G1  219776       // f32 [8][260]
#define SM_XS  228096       // f32 [8][8]
#define SM_H1F 228352       // f32 [8][64]
#define SMEM_BYTES 230400

__device__ __forceinline__ void ldmx4(uint32_t r[4], uint32_t addr) {
    asm volatile("ldmatrix.sync.aligned.m8n8.x4.shared.b16 {%0,%1,%2,%3}, [%4];"
                 : "=r"(r[0]), "=r"(r[1]), "=r"(r[2]), "=r"(r[3]) : "r"(addr));
}
__device__ __forceinline__ void mma16816(float d[4], const uint32_t a[4],
                                         uint32_t b0, uint32_t b1) {
    asm volatile("mma.sync.aligned.m16n8k16.row.col.f32.bf16.bf16.f32 "
                 "{%0,%1,%2,%3}, {%4,%5,%6,%7}, {%8,%9}, {%0,%1,%2,%3};"
                 : "+f"(d[0]), "+f"(d[1]), "+f"(d[2]), "+f"(d[3])
                 : "r"(a[0]), "r"(a[1]), "r"(a[2]), "r"(a[3]), "r"(b0), "r"(b1));
}
__device__ __forceinline__ float tanha(float x) {
    float r; asm("tanh.approx.f32 %0, %1;" : "=f"(r) : "f"(x)); return r;
}
__device__ __forceinline__ float sigm_(float x) {
    return fmaf(0.5f, tanha(0.5f * x), 0.5f);
}
__device__ __forceinline__ void split_bf16(float v, __nv_bfloat16& hi, __nv_bfloat16& lo) {
    hi = __float2bfloat16(v);
    lo = __float2bfloat16(v - __bfloat162float(hi));
}
__device__ __forceinline__ void ffma2(unsigned long long& acc,
                                      unsigned long long a,
                                      unsigned long long w) {
    asm("fma.rn.f32x2 %0, %1, %2, %0;" : "+l"(acc) : "l"(a), "l"(w));
}
__device__ __forceinline__ float hsum2(unsigned long long v) {
    float lo, hi;
    asm("mov.b64 {%0, %1}, %2;" : "=f"(lo), "=f"(hi) : "l"(v));
    return lo + hi;
}

extern __shared__ char smem[];

__global__ void __launch_bounds__(NTHREADS, 1)
lstm_wmma_kernel(const float* __restrict__ x,
                 const float* __restrict__ w_ih0, const float* __restrict__ w_hh0,
                 const float* __restrict__ b_ih0, const float* __restrict__ b_hh0,
                 const float* __restrict__ w_ih1, const float* __restrict__ w_hh1,
                 const float* __restrict__ b_ih1, const float* __restrict__ b_hh1,
                 const float* __restrict__ w_fc,  const float* __restrict__ b_fc,
                 float* __restrict__ out)
{
    const int tid  = threadIdx.x;
    const int w    = tid >> 5;
    const int lane = tid & 31;
    const int b0   = blockIdx.x * BT;

    uint32_t smb;
    asm("{ .reg .u64 t; cvta.to.shared.u64 t, %1; cvt.u32.u64 %0, t; }"
        : "=r"(smb) : "l"(smem));

    // ---- zero B operand buffers ----
    for (int i = tid; i < (8 * B0S) / 4; i += NTHREADS) {
        ((uint32_t*)(smem + SM_B0H))[i] = 0;
        ((uint32_t*)(smem + SM_B0L))[i] = 0;
    }
    for (int i = tid; i < (8 * B1S) / 4; i += NTHREADS) {
        ((uint32_t*)(smem + SM_B1H))[i] = 0;
        ((uint32_t*)(smem + SM_B1L))[i] = 0;
    }

    // ---- stage weights as bf16 hi/lo ----
    for (int i = tid; i < 256 * 64; i += NTHREADS) {
        int r = i >> 6, k = i & 63;
        __nv_bfloat16 hi, lo; split_bf16(w_hh0[i], hi, lo);
        uint32_t a = r * W0S + k * 2;
        *(__nv_bfloat16*)(smem + SM_W0H + a) = hi;
        *(__nv_bfloat16*)(smem + SM_W0L + a) = lo;
    }
    for (int i = tid; i < 256 * 128; i += NTHREADS) {
        int r = i >> 7, k = i & 127;
        float v = (k < 64) ? w_ih1[r * 64 + k] : w_hh1[r * 64 + (k - 64)];
        __nv_bfloat16 hi, lo; split_bf16(v, hi, lo);
        uint32_t off = (uint32_t)(k * 2) ^ (uint32_t)((r & 7) << 4);
        uint32_t a = r * W1S + off;
        *(__nv_bfloat16*)(smem + SM_W1H + a) = hi;
        *(__nv_bfloat16*)(smem + SM_W1L + a) = lo;
    }

    // ---- per-thread row constants ----
    const float bias0r = b_ih0[tid] + b_hh0[tid];
    const float bias1r = b_ih1[tid] + b_hh1[tid];
    unsigned long long wx[4];
    {
        ulonglong2 t0 = ((const ulonglong2*)(w_ih0 + tid * IDIM))[0];
        ulonglong2 t1 = ((const ulonglong2*)(w_ih0 + tid * IDIM))[1];
        wx[0] = t0.x; wx[1] = t0.y; wx[2] = t1.x; wx[3] = t1.y;
    }

    float* g0f = (float*)(smem + SM_G0);
    float* g1f = (float*)(smem + SM_G1);
    float* xsf = (float*)(smem + SM_XS);
    float* h1f = (float*)(smem + SM_H1F);

    // ---- prologue: gates0 prestore for t=0 ----
    #pragma unroll
    for (int b = 0; b < 8; b++) {
        ulonglong2 a1 = ((const ulonglong2*)(x + (size_t)(b0 + b) * TSTEPS * IDIM))[0];
        ulonglong2 a2 = ((const ulonglong2*)(x + (size_t)(b0 + b) * TSTEPS * IDIM))[1];
        unsigned long long s = 0ull;
        ffma2(s, a1.x, wx[0]); ffma2(s, a1.y, wx[1]);
        ffma2(s, a2.x, wx[2]); ffma2(s, a2.y, wx[3]);
        g0f[b * GSTR + tid] = hsum2(s) + bias0r;
    }

    // mma lane geometry
    const int aRow  = lane & 15;
    const int aHalf = lane >> 4;
    const int bn    = lane >> 2;
    const int bq    = lane & 3;
    const int dq    = lane & 3, dg = lane >> 2;

    const int eb = w;
    float c0[2] = {0.f, 0.f}, c1[2] = {0.f, 0.f};

    __syncthreads();

    // ---- W0 A-frags resident in registers for all 512 steps ----
    uint32_t a0h[4][2][4], a0l[4][2][4];
    #pragma unroll
    for (int kt = 0; kt < 4; kt++) {
        #pragma unroll
        for (int mi = 0; mi < 2; mi++) {
            int mb = 16 * (2 * w + mi);
            uint32_t ro = (uint32_t)(mb + aRow) * W0S + kt * 32 + aHalf * 16;
            ldmx4(a0h[kt][mi], smb + SM_W0H + ro);
            ldmx4(a0l[kt][mi], smb + SM_W0L + ro);
        }
    }

    for (int t = 0; t < TSTEPS; t++) {
        // ================= PHASE A: GEMM0  gates0 += W0 @ h0 =================
        {
            float dhh[2][4] = {{0,0,0,0},{0,0,0,0}};
            float dhl[2][4] = {{0,0,0,0},{0,0,0,0}};
            float dlh[2][4] = {{0,0,0,0},{0,0,0,0}};
            #pragma unroll
            for (int kt = 0; kt < 4; kt++) {
                uint32_t boff = bn * B0S + kt * 32 + bq * 4;
                uint32_t bh0 = *(const uint32_t*)(smem + SM_B0H + boff);
                uint32_t bh1 = *(const uint32_t*)(smem + SM_B0H + boff + 16);
                uint32_t bl0 = *(const uint32_t*)(smem + SM_B0L + boff);
                uint32_t bl1 = *(const uint32_t*)(smem + SM_B0L + boff + 16);
                #pragma unroll
                for (int mi = 0; mi < 2; mi++) {
                    mma16816(dhh[mi], a0h[kt][mi], bh0, bh1);
                    mma16816(dhl[mi], a0h[kt][mi], bl0, bl1);
                    mma16816(dlh[mi], a0l[kt][mi], bh0, bh1);
                }
            }
            #pragma unroll
            for (int mi = 0; mi < 2; mi++) {
                int mb = 16 * (2 * w + mi);
                #pragma unroll
                for (int e = 0; e < 4; e++) {
                    float d = (dhh[mi][e] + dhl[mi][e]) + dlh[mi][e];
                    int gb = 2 * dq + (e & 1);
                    int gc = mb + dg + (e >> 1) * 8;
                    g0f[gb * GSTR + gc] += d;
                }
            }
        }
        __syncthreads();

        // ================= PHASE B: elem0 + bias1 prestore =================
        {
            const float* g = g0f + eb * GSTR;
            #pragma unroll
            for (int j = 0; j < 2; j++) {
                int h = lane + 32 * j;
                float iv = sigm_(g[h]);
                float fv = sigm_(g[h + 64]);
                float gv = tanha(g[h + 128]);
                float ov = sigm_(g[h + 192]);
                c0[j] = fv * c0[j] + iv * gv;
                float hv = ov * tanha(c0[j]);
                __nv_bfloat16 hi, lo; split_bf16(hv, hi, lo);
                *(__nv_bfloat16*)(smem + SM_B0H + eb * B0S + h * 2) = hi;
                *(__nv_bfloat16*)(smem + SM_B0L + eb * B0S + h * 2) = lo;
                *(__nv_bfloat16*)(smem + SM_B1H + eb * B1S + h * 2) = hi;
                *(__nv_bfloat16*)(smem + SM_B1L + eb * B1S + h * 2) = lo;
            }
            #pragma unroll
            for (int b = 0; b < 8; b++) g1f[b * GSTR + tid] = bias1r;
        }
        __syncthreads();

        // ================= PHASE C: GEMM1  gates1 += W1 @ [h0new|h1old] =================
        if (tid < 16 && t + 1 < TSTEPS) {
            int b = tid >> 1, qq = tid & 1;
            float4 v = *(const float4*)(x + (size_t)(b0 + b) * TSTEPS * IDIM
                                          + (size_t)(t + 1) * IDIM + qq * 4);
            *(float4*)(xsf + b * 8 + qq * 4) = v;
        }
        {
            float dhh[2][4] = {{0,0,0,0},{0,0,0,0}};
            float dhl[2][4] = {{0,0,0,0},{0,0,0,0}};
            float dlh[2][4] = {{0,0,0,0},{0,0,0,0}};
            #pragma unroll
            for (int kt = 0; kt < 8; kt++) {
                uint32_t boff = bn * B1S + kt * 32 + bq * 4;
                uint32_t bh0 = *(const uint32_t*)(smem + SM_B1H + boff);
                uint32_t bh1 = *(const uint32_t*)(smem + SM_B1H + boff + 16);
                uint32_t bl0 = *(const uint32_t*)(smem + SM_B1L + boff);
                uint32_t bl1 = *(const uint32_t*)(smem + SM_B1L + boff + 16);
                #pragma unroll
                for (int mi = 0; mi < 2; mi++) {
                    int mb = 16 * (2 * w + mi);
                    int row = mb + aRow;
                    uint32_t off = (uint32_t)(kt * 32 + aHalf * 16)
                                 ^ (uint32_t)((row & 7) << 4);
                    uint32_t ro = (uint32_t)row * W1S + off;
                    uint32_t ah[4], al[4];
                    ldmx4(ah, smb + SM_W1H + ro);
                    ldmx4(al, smb + SM_W1L + ro);
                    mma16816(dhh[mi], ah, bh0, bh1);
                    mma16816(dhl[mi], ah, bl0, bl1);
                    mma16816(dlh[mi], al, bh0, bh1);
                }
            }
            #pragma unroll
            for (int mi = 0; mi < 2; mi++) {
                int mb = 16 * (2 * w + mi);
                #pragma unroll
                for (int e = 0; e < 4; e++) {
                    float d = (dhh[mi][e] + dhl[mi][e]) + dlh[mi][e];
                    int gb = 2 * dq + (e & 1);
                    int gc = mb + dg + (e >> 1) * 8;
                    g1f[gb * GSTR + gc] += d;
                }
            }
        }
        __syncthreads();

        // ================= PHASE D: elem1 + xg(t+1)+bias0 prestore =================
        {
            const float* g = g1f + eb * GSTR;
            #pragma unroll
            for (int j = 0; j < 2; j++) {
                int h = lane + 32 * j;
                float iv = sigm_(g[h]);
                float fv = sigm_(g[h + 64]);
                float gv = tanha(g[h + 128]);
                float ov = sigm_(g[h + 192]);
                c1[j] = fv * c1[j] + iv * gv;
                float hv = ov * tanha(c1[j]);
                __nv_bfloat16 hi, lo; split_bf16(hv, hi, lo);
                *(__nv_bfloat16*)(smem + SM_B1H + eb * B1S + 128 + h * 2) = hi;
                *(__nv_bfloat16*)(smem + SM_B1L + eb * B1S + 128 + h * 2) = lo;
                if (t == TSTEPS - 1) h1f[eb * HID + h] = hv;
            }
            if (t + 1 < TSTEPS) {
                const ulonglong2* xq = (const ulonglong2*)xsf;
                #pragma unroll
                for (int b = 0; b < 8; b++) {
                    ulonglong2 a1 = xq[b * 2];
                    ulonglong2 a2 = xq[b * 2 + 1];
                    unsigned long long s = 0ull;
                    ffma2(s, a1.x, wx[0]); ffma2(s, a1.y, wx[1]);
                    ffma2(s, a2.x, wx[2]); ffma2(s, a2.y, wx[3]);
                    g0f[b * GSTR + tid] = hsum2(s) + bias0r;
                }
            }
        }
        __syncthreads();
    }

    // ================= FC: out = h1_final @ w_fc^T + b_fc =================
    if (tid < BT * ODIM) {
        int b = tid / ODIM, o = tid % ODIM;
        const float* hrow = h1f + b * HID;
        const float* wrow = w_fc + o * HID;
        float s = b_fc[o];
        #pragma unroll 16
        for (int k = 0; k < HID; k++) s = fmaf(hrow[k], wrow[k], s);
        out[(size_t)(b0 + b) * ODIM + o] = s;
    }
}

extern "C" void kernel_launch(void* const* d_in, const int* in_sizes, int n_in,
                              void* d_out, int out_size)
{
    (void)in_sizes; (void)n_in; (void)out_size;
    const float* x     = (const float*)d_in[0];
    const float* w_ih0 = (const float*)d_in[1];
    const float* w_hh0 = (const float*)d_in[2];
    const float* b_ih0 = (const float*)d_in[3];
    const float* b_hh0 = (const float*)d_in[4];
    const float* w_ih1 = (const float*)d_in[5];
    const float* w_hh1 = (const float*)d_in[6];
    const float* b_ih1 = (const float*)d_in[7];
    const float* b_hh1 = (const float*)d_in[8];
    const float* w_fc  = (const float*)d_in[9];
    const float* b_fc  = (const float*)d_in[10];

    cudaFuncSetAttribute(lstm_wmma_kernel,
                         cudaFuncAttributeMaxDynamicSharedMemorySize, SMEM_BYTES);
    lstm_wmma_kernel<<<NB, NTHREADS, SMEM_BYTES>>>(
        x, w_ih0, w_hh0, b_ih0, b_hh0, w_ih1, w_hh1, b_ih1, b_hh1, w_fc, b_fc,
        (float*)d_out);
}

// round 11
// speedup vs baseline: 3.5712x; 1.0395x over previous
#include <cuda_runtime.h>
#include <cuda_bf16.h>
#include <cstdint>
#include <cstddef>

// LSTM_824633721296: 2-layer LSTM (B=1024, T=512, I=8, H=64) + FC (O=10)
// Warp-level tensor cores (mma.sync.m16n8k16 bf16, fp32 accum), hi/lo 3-term.
// Round-11: 512 threads (16 warps, 4/SMSP), ONE m-tile per warp -> half the
// serial work per warp, 2x warps for latency hiding. W0 A-frags register-
// resident; 3 independent accumulation chains per D-frag.
// x-part exact fp32. tanh.approx activations.

#define BT       8
#define NB       128
#define NTHREADS 512
#define HID      64
#define TSTEPS   512
#define IDIM     8
#define ODIM     10

#define GSTR 260            // gate buffer stride (floats)
#define W0S  144            // W0 row stride bytes (64 bf16 + pad)
#define W1S  256            // W1 row stride bytes (128 bf16, XOR-swizzled)
#define B0S  144            // B0 row stride bytes
#define B1S  272            // B1 row stride bytes

// smem byte offsets
#define SM_W0H 0            // [256][144]
#define SM_W0L 36864
#define SM_W1H 73728        // [256][256] swizzled
#define SM_W1L 139264
#define SM_B0H 204800       // [8][144]  h0 (layer-0 B operand)
#define SM_B0L 205952
#define SM_B1H 207104       // [8][272]  [h0new | h1old] (layer-1 B operand)
#define SM_B1L 209280
#define SM_G0  211456       // f32 [8][260]
#define SM_G1  219776       // f32 [8][260]
#define SM_XS  228096       // f32 [8][8]
#define SM_H1F 228352       // f32 [8][64]
#define SMEM_BYTES 230400

__device__ __forceinline__ void ldmx4(uint32_t r[4], uint32_t addr) {
    asm volatile("ldmatrix.sync.aligned.m8n8.x4.shared.b16 {%0,%1,%2,%3}, [%4];"
                 : "=r"(r[0]), "=r"(r[1]), "=r"(r[2]), "=r"(r[3]) : "r"(addr));
}
__device__ __forceinline__ void mma16816(float d[4], const uint32_t a[4],
                                         uint32_t b0, uint32_t b1) {
    asm volatile("mma.sync.aligned.m16n8k16.row.col.f32.bf16.bf16.f32 "
                 "{%0,%1,%2,%3}, {%4,%5,%6,%7}, {%8,%9}, {%0,%1,%2,%3};"
                 : "+f"(d[0]), "+f"(d[1]), "+f"(d[2]), "+f"(d[3])
                 : "r"(a[0]), "r"(a[1]), "r"(a[2]), "r"(a[3]), "r"(b0), "r"(b1));
}
__device__ __forceinline__ float tanha(float x) {
    float r; asm("tanh.approx.f32 %0, %1;" : "=f"(r) : "f"(x)); return r;
}
__device__ __forceinline__ float sigm_(float x) {
    return fmaf(0.5f, tanha(0.5f * x), 0.5f);
}
__device__ __forceinline__ void split_bf16(float v, __nv_bfloat16& hi, __nv_bfloat16& lo) {
    hi = __float2bfloat16(v);
    lo = __float2bfloat16(v - __bfloat162float(hi));
}
__device__ __forceinline__ void ffma2(unsigned long long& acc,
                                      unsigned long long a,
                                      unsigned long long w) {
    asm("fma.rn.f32x2 %0, %1, %2, %0;" : "+l"(acc) : "l"(a), "l"(w));
}
__device__ __forceinline__ float hsum2(unsigned long long v) {
    float lo, hi;
    asm("mov.b64 {%0, %1}, %2;" : "=f"(lo), "=f"(hi) : "l"(v));
    return lo + hi;
}

extern __shared__ char smem[];

__global__ void __launch_bounds__(NTHREADS, 1)
lstm_wmma_kernel(const float* __restrict__ x,
                 const float* __restrict__ w_ih0, const float* __restrict__ w_hh0,
                 const float* __restrict__ b_ih0, const float* __restrict__ b_hh0,
                 const float* __restrict__ w_ih1, const float* __restrict__ w_hh1,
                 const float* __restrict__ b_ih1, const float* __restrict__ b_hh1,
                 const float* __restrict__ w_fc,  const float* __restrict__ b_fc,
                 float* __restrict__ out)
{
    const int tid  = threadIdx.x;
    const int w    = tid >> 5;          // warp 0..15 = m-tile
    const int lane = tid & 31;
    const int b0   = blockIdx.x * BT;

    uint32_t smb;
    asm("{ .reg .u64 t; cvta.to.shared.u64 t, %1; cvt.u32.u64 %0, t; }"
        : "=r"(smb) : "l"(smem));

    // ---- zero B operand buffers ----
    for (int i = tid; i < (8 * B0S) / 4; i += NTHREADS) {
        ((uint32_t*)(smem + SM_B0H))[i] = 0;
        ((uint32_t*)(smem + SM_B0L))[i] = 0;
    }
    for (int i = tid; i < (8 * B1S) / 4; i += NTHREADS) {
        ((uint32_t*)(smem + SM_B1H))[i] = 0;
        ((uint32_t*)(smem + SM_B1L))[i] = 0;
    }

    // ---- stage weights as bf16 hi/lo ----
    for (int i = tid; i < 256 * 64; i += NTHREADS) {
        int r = i >> 6, k = i & 63;
        __nv_bfloat16 hi, lo; split_bf16(w_hh0[i], hi, lo);
        uint32_t a = r * W0S + k * 2;
        *(__nv_bfloat16*)(smem + SM_W0H + a) = hi;
        *(__nv_bfloat16*)(smem + SM_W0L + a) = lo;
    }
    for (int i = tid; i < 256 * 128; i += NTHREADS) {
        int r = i >> 7, k = i & 127;
        float v = (k < 64) ? w_ih1[r * 64 + k] : w_hh1[r * 64 + (k - 64)];
        __nv_bfloat16 hi, lo; split_bf16(v, hi, lo);
        uint32_t off = (uint32_t)(k * 2) ^ (uint32_t)((r & 7) << 4);
        uint32_t a = r * W1S + off;
        *(__nv_bfloat16*)(smem + SM_W1H + a) = hi;
        *(__nv_bfloat16*)(smem + SM_W1L + a) = lo;
    }

    // ---- per-thread row constants: row = tid&255, batches (tid>>8)*4.. ----
    const int rowc = tid & 255;
    const int bb4  = (tid >> 8) * 4;
    const float bias0r = b_ih0[rowc] + b_hh0[rowc];
    const float bias1r = b_ih1[rowc] + b_hh1[rowc];
    unsigned long long wx[4];
    {
        ulonglong2 t0 = ((const ulonglong2*)(w_ih0 + rowc * IDIM))[0];
        ulonglong2 t1 = ((const ulonglong2*)(w_ih0 + rowc * IDIM))[1];
        wx[0] = t0.x; wx[1] = t0.y; wx[2] = t1.x; wx[3] = t1.y;
    }

    float* g0f = (float*)(smem + SM_G0);
    float* g1f = (float*)(smem + SM_G1);
    float* xsf = (float*)(smem + SM_XS);
    float* h1f = (float*)(smem + SM_H1F);

    // ---- prologue: gates0 prestore for t=0 (4 batches per thread) ----
    #pragma unroll
    for (int bi = 0; bi < 4; bi++) {
        int b = bb4 + bi;
        ulonglong2 a1 = ((const ulonglong2*)(x + (size_t)(b0 + b) * TSTEPS * IDIM))[0];
        ulonglong2 a2 = ((const ulonglong2*)(x + (size_t)(b0 + b) * TSTEPS * IDIM))[1];
        unsigned long long s = 0ull;
        ffma2(s, a1.x, wx[0]); ffma2(s, a1.y, wx[1]);
        ffma2(s, a2.x, wx[2]); ffma2(s, a2.y, wx[3]);
        g0f[b * GSTR + rowc] = hsum2(s) + bias0r;
    }

    // mma lane geometry (1 m-tile per warp: rows 16w .. 16w+15)
    const int mb    = 16 * w;
    const int aRow  = lane & 15;
    const int aHalf = lane >> 4;
    const int bn    = lane >> 2;
    const int bq    = lane & 3;
    const int dq    = lane & 3, dg = lane >> 2;

    // elem geometry: 1 element per layer per thread
    const int eb = tid >> 6;     // batch 0..7
    const int eh = tid & 63;     // h index
    float c0 = 0.f, c1 = 0.f;

    __syncthreads();

    // ---- W0 A-frags resident in registers for all 512 steps (1 m-tile) ----
    uint32_t a0h[4][4], a0l[4][4];
    #pragma unroll
    for (int kt = 0; kt < 4; kt++) {
        uint32_t ro = (uint32_t)(mb + aRow) * W0S + kt * 32 + aHalf * 16;
        ldmx4(a0h[kt], smb + SM_W0H + ro);
        ldmx4(a0l[kt], smb + SM_W0L + ro);
    }

    for (int t = 0; t < TSTEPS; t++) {
        // ================= PHASE A: GEMM0  gates0 += W0 @ h0 =================
        {
            float dhh[4] = {0,0,0,0}, dhl[4] = {0,0,0,0}, dlh[4] = {0,0,0,0};
            #pragma unroll
            for (int kt = 0; kt < 4; kt++) {
                uint32_t boff = bn * B0S + kt * 32 + bq * 4;
                uint32_t bh0 = *(const uint32_t*)(smem + SM_B0H + boff);
                uint32_t bh1 = *(const uint32_t*)(smem + SM_B0H + boff + 16);
                uint32_t bl0 = *(const uint32_t*)(smem + SM_B0L + boff);
                uint32_t bl1 = *(const uint32_t*)(smem + SM_B0L + boff + 16);
                mma16816(dhh, a0h[kt], bh0, bh1);
                mma16816(dhl, a0h[kt], bl0, bl1);
                mma16816(dlh, a0l[kt], bh0, bh1);
            }
            #pragma unroll
            for (int e = 0; e < 4; e++) {
                float d = (dhh[e] + dhl[e]) + dlh[e];
                int gb = 2 * dq + (e & 1);
                int gc = mb + dg + (e >> 1) * 8;
                g0f[gb * GSTR + gc] += d;
            }
        }
        __syncthreads();

        // ================= PHASE B: elem0 + bias1 prestore =================
        {
            const float* g = g0f + eb * GSTR;
            float iv = sigm_(g[eh]);
            float fv = sigm_(g[eh + 64]);
            float gv = tanha(g[eh + 128]);
            float ov = sigm_(g[eh + 192]);
            c0 = fv * c0 + iv * gv;
            float hv = ov * tanha(c0);
            __nv_bfloat16 hi, lo; split_bf16(hv, hi, lo);
            *(__nv_bfloat16*)(smem + SM_B0H + eb * B0S + eh * 2) = hi;  // next GEMM0
            *(__nv_bfloat16*)(smem + SM_B0L + eb * B0S + eh * 2) = lo;
            *(__nv_bfloat16*)(smem + SM_B1H + eb * B1S + eh * 2) = hi;  // this GEMM1
            *(__nv_bfloat16*)(smem + SM_B1L + eb * B1S + eh * 2) = lo;
            #pragma unroll
            for (int bi = 0; bi < 4; bi++)
                g1f[(bb4 + bi) * GSTR + rowc] = bias1r;
        }
        __syncthreads();

        // ================= PHASE C: GEMM1  gates1 += W1 @ [h0new|h1old] =================
        if (tid < 16 && t + 1 < TSTEPS) {
            int b = tid >> 1, qq = tid & 1;
            float4 v = *(const float4*)(x + (size_t)(b0 + b) * TSTEPS * IDIM
                                          + (size_t)(t + 1) * IDIM + qq * 4);
            *(float4*)(xsf + b * 8 + qq * 4) = v;
        }
        {
            float dhh[4] = {0,0,0,0}, dhl[4] = {0,0,0,0}, dlh[4] = {0,0,0,0};
            #pragma unroll
            for (int kt = 0; kt < 8; kt++) {
                uint32_t boff = bn * B1S + kt * 32 + bq * 4;
                uint32_t bh0 = *(const uint32_t*)(smem + SM_B1H + boff);
                uint32_t bh1 = *(const uint32_t*)(smem + SM_B1H + boff + 16);
                uint32_t bl0 = *(const uint32_t*)(smem + SM_B1L + boff);
                uint32_t bl1 = *(const uint32_t*)(smem + SM_B1L + boff + 16);
                int row = mb + aRow;
                uint32_t off = (uint32_t)(kt * 32 + aHalf * 16)
                             ^ (uint32_t)((row & 7) << 4);
                uint32_t ro = (uint32_t)row * W1S + off;
                uint32_t ah[4], al[4];
                ldmx4(ah, smb + SM_W1H + ro);
                ldmx4(al, smb + SM_W1L + ro);
                mma16816(dhh, ah, bh0, bh1);
                mma16816(dhl, ah, bl0, bl1);
                mma16816(dlh, al, bh0, bh1);
            }
            #pragma unroll
            for (int e = 0; e < 4; e++) {
                float d = (dhh[e] + dhl[e]) + dlh[e];
                int gb = 2 * dq + (e & 1);
                int gc = mb + dg + (e >> 1) * 8;
                g1f[gb * GSTR + gc] += d;
            }
        }
        __syncthreads();

        // ================= PHASE D: elem1 + xg(t+1)+bias0 prestore =================
        {
            const float* g = g1f + eb * GSTR;
            float iv = sigm_(g[eh]);
            float fv = sigm_(g[eh + 64]);
            float gv = tanha(g[eh + 128]);
            float ov = sigm_(g[eh + 192]);
            c1 = fv * c1 + iv * gv;
            float hv = ov * tanha(c1);
            __nv_bfloat16 hi, lo; split_bf16(hv, hi, lo);
            *(__nv_bfloat16*)(smem + SM_B1H + eb * B1S + 128 + eh * 2) = hi;
            *(__nv_bfloat16*)(smem + SM_B1L + eb * B1S + 128 + eh * 2) = lo;
            if (t == TSTEPS - 1) h1f[eb * HID + eh] = hv;

            if (t + 1 < TSTEPS) {
                const ulonglong2* xq = (const ulonglong2*)xsf;
                #pragma unroll
                for (int bi = 0; bi < 4; bi++) {
                    int b = bb4 + bi;
                    ulonglong2 a1 = xq[b * 2];
                    ulonglong2 a2 = xq[b * 2 + 1];
                    unsigned long long s = 0ull;
                    ffma2(s, a1.x, wx[0]); ffma2(s, a1.y, wx[1]);
                    ffma2(s, a2.x, wx[2]); ffma2(s, a2.y, wx[3]);
                    g0f[b * GSTR + rowc] = hsum2(s) + bias0r;
                }
            }
        }
        __syncthreads();
    }

    // ================= FC: out = h1_final @ w_fc^T + b_fc =================
    if (tid < BT * ODIM) {
        int b = tid / ODIM, o = tid % ODIM;
        const float* hrow = h1f + b * HID;
        const float* wrow = w_fc + o * HID;
        float s = b_fc[o];
        #pragma unroll 16
        for (int k = 0; k < HID; k++) s = fmaf(hrow[k], wrow[k], s);
        out[(size_t)(b0 + b) * ODIM + o] = s;
    }
}

extern "C" void kernel_launch(void* const* d_in, const int* in_sizes, int n_in,
                              void* d_out, int out_size)
{
    (void)in_sizes; (void)n_in; (void)out_size;
    const float* x     = (const float*)d_in[0];
    const float* w_ih0 = (const float*)d_in[1];
    const float* w_hh0 = (const float*)d_in[2];
    const float* b_ih0 = (const float*)d_in[3];
    const float* b_hh0 = (const float*)d_in[4];
    const float* w_ih1 = (const float*)d_in[5];
    const float* w_hh1 = (const float*)d_in[6];
    const float* b_ih1 = (const float*)d_in[7];
    const float* b_hh1 = (const float*)d_in[8];
    const float* w_fc  = (const float*)d_in[9];
    const float* b_fc  = (const float*)d_in[10];

    cudaFuncSetAttribute(lstm_wmma_kernel,
                         cudaFuncAttributeMaxDynamicSharedMemorySize, SMEM_BYTES);
    lstm_wmma_kernel<<<NB, NTHREADS, SMEM_BYTES>>>(
        x, w_ih0, w_hh0, b_ih0, b_hh0, w_ih1, w_hh1, b_ih1, b_hh1, w_fc, b_fc,
        (float*)d_out);
}

// round 12
// speedup vs baseline: 5.2141x; 1.4600x over previous
#include <cuda_runtime.h>
#include <cuda_bf16.h>
#include <cstdint>
#include <cstddef>

// LSTM_824633721296: 2-layer LSTM (B=1024, T=512, I=8, H=64) + FC (O=10)
// Round-12: mma.sync m16n8k16, weights plain bf16 (A-frags ALL register-
// resident -> ZERO ldmatrix in the loop), h state kept as bf16 hi/lo pair
// (2-term: W@h_hi + W@h_lo, fp32 accum). 512 threads, 1 m-tile/warp.
// x-part exact fp32. tanh.approx activations.

#define BT       8
#define NB       128
#define NTHREADS 512
#define HID      64
#define TSTEPS   512
#define IDIM     8
#define ODIM     10

#define GSTR 260            // gate buffer stride (floats)
#define W0S  144            // W0 row stride bytes (64 bf16 + pad)
#define W1S  256            // W1 row stride bytes (128 bf16, XOR-swizzled)
#define B0S  144            // B0 row stride bytes
#define B1S  272            // B1 row stride bytes

// smem byte offsets
#define SM_W0H 0            // [256][144] = 36864 (staging for frag load)
#define SM_W1H 36864        // [256][256] swizzled = 65536
#define SM_B0H 102400       // [8][144]  h0 hi
#define SM_B0L 103552       // [8][144]  h0 lo
#define SM_B1H 104704       // [8][272]  [h0new | h1old] hi
#define SM_B1L 106880       // [8][272]  lo
#define SM_G0  109056       // f32 [8][260]
#define SM_G1  117376       // f32 [8][260]
#define SM_XS  125696       // f32 [8][8]
#define SM_H1F 125952       // f32 [8][64]
#define SMEM_BYTES 128000

__device__ __forceinline__ void ldmx4(uint32_t r[4], uint32_t addr) {
    asm volatile("ldmatrix.sync.aligned.m8n8.x4.shared.b16 {%0,%1,%2,%3}, [%4];"
                 : "=r"(r[0]), "=r"(r[1]), "=r"(r[2]), "=r"(r[3]) : "r"(addr));
}
__device__ __forceinline__ void mma16816(float d[4], const uint32_t a[4],
                                         uint32_t b0, uint32_t b1) {
    asm volatile("mma.sync.aligned.m16n8k16.row.col.f32.bf16.bf16.f32 "
                 "{%0,%1,%2,%3}, {%4,%5,%6,%7}, {%8,%9}, {%0,%1,%2,%3};"
                 : "+f"(d[0]), "+f"(d[1]), "+f"(d[2]), "+f"(d[3])
                 : "r"(a[0]), "r"(a[1]), "r"(a[2]), "r"(a[3]), "r"(b0), "r"(b1));
}
__device__ __forceinline__ float tanha(float x) {
    float r; asm("tanh.approx.f32 %0, %1;" : "=f"(r) : "f"(x)); return r;
}
__device__ __forceinline__ float sigm_(float x) {
    return fmaf(0.5f, tanha(0.5f * x), 0.5f);
}
__device__ __forceinline__ void split_bf16(float v, __nv_bfloat16& hi, __nv_bfloat16& lo) {
    hi = __float2bfloat16(v);
    lo = __float2bfloat16(v - __bfloat162float(hi));
}
__device__ __forceinline__ void ffma2(unsigned long long& acc,
                                      unsigned long long a,
                                      unsigned long long w) {
    asm("fma.rn.f32x2 %0, %1, %2, %0;" : "+l"(acc) : "l"(a), "l"(w));
}
__device__ __forceinline__ float hsum2(unsigned long long v) {
    float lo, hi;
    asm("mov.b64 {%0, %1}, %2;" : "=f"(lo), "=f"(hi) : "l"(v));
    return lo + hi;
}

extern __shared__ char smem[];

__global__ void __launch_bounds__(NTHREADS, 1)
lstm_wmma_kernel(const float* __restrict__ x,
                 const float* __restrict__ w_ih0, const float* __restrict__ w_hh0,
                 const float* __restrict__ b_ih0, const float* __restrict__ b_hh0,
                 const float* __restrict__ w_ih1, const float* __restrict__ w_hh1,
                 const float* __restrict__ b_ih1, const float* __restrict__ b_hh1,
                 const float* __restrict__ w_fc,  const float* __restrict__ b_fc,
                 float* __restrict__ out)
{
    const int tid  = threadIdx.x;
    const int w    = tid >> 5;          // warp 0..15 = m-tile
    const int lane = tid & 31;
    const int b0   = blockIdx.x * BT;

    uint32_t smb;
    asm("{ .reg .u64 t; cvta.to.shared.u64 t, %1; cvt.u32.u64 %0, t; }"
        : "=r"(smb) : "l"(smem));

    // ---- zero B operand buffers ----
    for (int i = tid; i < (8 * B0S) / 4; i += NTHREADS) {
        ((uint32_t*)(smem + SM_B0H))[i] = 0;
        ((uint32_t*)(smem + SM_B0L))[i] = 0;
    }
    for (int i = tid; i < (8 * B1S) / 4; i += NTHREADS) {
        ((uint32_t*)(smem + SM_B1H))[i] = 0;
        ((uint32_t*)(smem + SM_B1L))[i] = 0;
    }

    // ---- stage weights as plain bf16 ----
    for (int i = tid; i < 256 * 64; i += NTHREADS) {
        int r = i >> 6, k = i & 63;
        *(__nv_bfloat16*)(smem + SM_W0H + r * W0S + k * 2) = __float2bfloat16(w_hh0[i]);
    }
    for (int i = tid; i < 256 * 128; i += NTHREADS) {
        int r = i >> 7, k = i & 127;
        float v = (k < 64) ? w_ih1[r * 64 + k] : w_hh1[r * 64 + (k - 64)];
        uint32_t off = (uint32_t)(k * 2) ^ (uint32_t)((r & 7) << 4);
        *(__nv_bfloat16*)(smem + SM_W1H + r * W1S + off) = __float2bfloat16(v);
    }

    // ---- per-thread row constants: row = tid&255, batches (tid>>8)*4.. ----
    const int rowc = tid & 255;
    const int bb4  = (tid >> 8) * 4;
    const float bias0r = b_ih0[rowc] + b_hh0[rowc];
    const float bias1r = b_ih1[rowc] + b_hh1[rowc];
    unsigned long long wx[4];
    {
        ulonglong2 t0 = ((const ulonglong2*)(w_ih0 + rowc * IDIM))[0];
        ulonglong2 t1 = ((const ulonglong2*)(w_ih0 + rowc * IDIM))[1];
        wx[0] = t0.x; wx[1] = t0.y; wx[2] = t1.x; wx[3] = t1.y;
    }

    float* g0f = (float*)(smem + SM_G0);
    float* g1f = (float*)(smem + SM_G1);
    float* xsf = (float*)(smem + SM_XS);
    float* h1f = (float*)(smem + SM_H1F);

    // ---- prologue: gates0 prestore for t=0 (4 batches per thread) ----
    #pragma unroll
    for (int bi = 0; bi < 4; bi++) {
        int b = bb4 + bi;
        ulonglong2 a1 = ((const ulonglong2*)(x + (size_t)(b0 + b) * TSTEPS * IDIM))[0];
        ulonglong2 a2 = ((const ulonglong2*)(x + (size_t)(b0 + b) * TSTEPS * IDIM))[1];
        unsigned long long s = 0ull;
        ffma2(s, a1.x, wx[0]); ffma2(s, a1.y, wx[1]);
        ffma2(s, a2.x, wx[2]); ffma2(s, a2.y, wx[3]);
        g0f[b * GSTR + rowc] = hsum2(s) + bias0r;
    }

    // mma lane geometry (rows 16w .. 16w+15)
    const int mb    = 16 * w;
    const int aRow  = lane & 15;
    const int aHalf = lane >> 4;
    const int bn    = lane >> 2;
    const int bq    = lane & 3;
    const int dq    = lane & 3, dg = lane >> 2;

    // elem geometry
    const int eb = tid >> 6;     // batch 0..7
    const int eh = tid & 63;     // h index
    float c0 = 0.f, c1 = 0.f;

    __syncthreads();

    // ---- ALL A-frags (bf16 weights) resident in registers for 512 steps ----
    uint32_t a0h[4][4];   // W0: 4 k-tiles
    uint32_t a1h[8][4];   // W1: 8 k-tiles
    #pragma unroll
    for (int kt = 0; kt < 4; kt++) {
        uint32_t ro = (uint32_t)(mb + aRow) * W0S + kt * 32 + aHalf * 16;
        ldmx4(a0h[kt], smb + SM_W0H + ro);
    }
    #pragma unroll
    for (int kt = 0; kt < 8; kt++) {
        int row = mb + aRow;
        uint32_t off = (uint32_t)(kt * 32 + aHalf * 16) ^ (uint32_t)((row & 7) << 4);
        ldmx4(a1h[kt], smb + SM_W1H + (uint32_t)row * W1S + off);
    }

    for (int t = 0; t < TSTEPS; t++) {
        // ================= PHASE A: GEMM0  gates0 += W0 @ (h0hi + h0lo) =================
        {
            float dhh[4] = {0,0,0,0}, dhl[4] = {0,0,0,0};
            #pragma unroll
            for (int kt = 0; kt < 4; kt++) {
                uint32_t boff = bn * B0S + kt * 32 + bq * 4;
                uint32_t bh0 = *(const uint32_t*)(smem + SM_B0H + boff);
                uint32_t bh1 = *(const uint32_t*)(smem + SM_B0H + boff + 16);
                uint32_t bl0 = *(const uint32_t*)(smem + SM_B0L + boff);
                uint32_t bl1 = *(const uint32_t*)(smem + SM_B0L + boff + 16);
                mma16816(dhh, a0h[kt], bh0, bh1);
                mma16816(dhl, a0h[kt], bl0, bl1);
            }
            #pragma unroll
            for (int e = 0; e < 4; e++) {
                float d = dhh[e] + dhl[e];
                int gb = 2 * dq + (e & 1);
                int gc = mb + dg + (e >> 1) * 8;
                g0f[gb * GSTR + gc] += d;
            }
        }
        __syncthreads();

        // ================= PHASE B: elem0 + bias1 prestore =================
        {
            const float* g = g0f + eb * GSTR;
            float iv = sigm_(g[eh]);
            float fv = sigm_(g[eh + 64]);
            float gv = tanha(g[eh + 128]);
            float ov = sigm_(g[eh + 192]);
            c0 = fv * c0 + iv * gv;
            float hv = ov * tanha(c0);
            __nv_bfloat16 hi, lo; split_bf16(hv, hi, lo);
            *(__nv_bfloat16*)(smem + SM_B0H + eb * B0S + eh * 2) = hi;  // next GEMM0
            *(__nv_bfloat16*)(smem + SM_B0L + eb * B0S + eh * 2) = lo;
            *(__nv_bfloat16*)(smem + SM_B1H + eb * B1S + eh * 2) = hi;  // this GEMM1
            *(__nv_bfloat16*)(smem + SM_B1L + eb * B1S + eh * 2) = lo;
            #pragma unroll
            for (int bi = 0; bi < 4; bi++)
                g1f[(bb4 + bi) * GSTR + rowc] = bias1r;
        }
        __syncthreads();

        // ================= PHASE C: GEMM1  gates1 += W1 @ [h0new|h1old] =================
        if (tid < 16 && t + 1 < TSTEPS) {
            int b = tid >> 1, qq = tid & 1;
            float4 v = *(const float4*)(x + (size_t)(b0 + b) * TSTEPS * IDIM
                                          + (size_t)(t + 1) * IDIM + qq * 4);
            *(float4*)(xsf + b * 8 + qq * 4) = v;
        }
        {
            float dhh[4] = {0,0,0,0}, dhl[4] = {0,0,0,0};
            #pragma unroll
            for (int kt = 0; kt < 8; kt++) {
                uint32_t boff = bn * B1S + kt * 32 + bq * 4;
                uint32_t bh0 = *(const uint32_t*)(smem + SM_B1H + boff);
                uint32_t bh1 = *(const uint32_t*)(smem + SM_B1H + boff + 16);
                uint32_t bl0 = *(const uint32_t*)(smem + SM_B1L + boff);
                uint32_t bl1 = *(const uint32_t*)(smem + SM_B1L + boff + 16);
                mma16816(dhh, a1h[kt], bh0, bh1);
                mma16816(dhl, a1h[kt], bl0, bl1);
            }
            #pragma unroll
            for (int e = 0; e < 4; e++) {
                float d = dhh[e] + dhl[e];
                int gb = 2 * dq + (e & 1);
                int gc = mb + dg + (e >> 1) * 8;
                g1f[gb * GSTR + gc] += d;
            }
        }
        __syncthreads();

        // ================= PHASE D: elem1 + xg(t+1)+bias0 prestore =================
        {
            const float* g = g1f + eb * GSTR;
            float iv = sigm_(g[eh]);
            float fv = sigm_(g[eh + 64]);
            float gv = tanha(g[eh + 128]);
            float ov = sigm_(g[eh + 192]);
            c1 = fv * c1 + iv * gv;
            float hv = ov * tanha(c1);
            __nv_bfloat16 hi, lo; split_bf16(hv, hi, lo);
            *(__nv_bfloat16*)(smem + SM_B1H + eb * B1S + 128 + eh * 2) = hi;
            *(__nv_bfloat16*)(smem + SM_B1L + eb * B1S + 128 + eh * 2) = lo;
            if (t == TSTEPS - 1) h1f[eb * HID + eh] = hv;

            if (t + 1 < TSTEPS) {
                const ulonglong2* xq = (const ulonglong2*)xsf;
                #pragma unroll
                for (int bi = 0; bi < 4; bi++) {
                    int b = bb4 + bi;
                    ulonglong2 a1 = xq[b * 2];
                    ulonglong2 a2 = xq[b * 2 + 1];
                    unsigned long long s = 0ull;
                    ffma2(s, a1.x, wx[0]); ffma2(s, a1.y, wx[1]);
                    ffma2(s, a2.x, wx[2]); ffma2(s, a2.y, wx[3]);
                    g0f[b * GSTR + rowc] = hsum2(s) + bias0r;
                }
            }
        }
        __syncthreads();
    }

    // ================= FC: out = h1_final @ w_fc^T + b_fc =================
    if (tid < BT * ODIM) {
        int b = tid / ODIM, o = tid % ODIM;
        const float* hrow = h1f + b * HID;
        const float* wrow = w_fc + o * HID;
        float s = b_fc[o];
        #pragma unroll 16
        for (int k = 0; k < HID; k++) s = fmaf(hrow[k], wrow[k], s);
        out[(size_t)(b0 + b) * ODIM + o] = s;
    }
}

extern "C" void kernel_launch(void* const* d_in, const int* in_sizes, int n_in,
                              void* d_out, int out_size)
{
    (void)in_sizes; (void)n_in; (void)out_size;
    const float* x     = (const float*)d_in[0];
    const float* w_ih0 = (const float*)d_in[1];
    const float* w_hh0 = (const float*)d_in[2];
    const float* b_ih0 = (const float*)d_in[3];
    const float* b_hh0 = (const float*)d_in[4];
    const float* w_ih1 = (const float*)d_in[5];
    const float* w_hh1 = (const float*)d_in[6];
    const float* b_ih1 = (const float*)d_in[7];
    const float* b_hh1 = (const float*)d_in[8];
    const float* w_fc  = (const float*)d_in[9];
    const float* b_fc  = (const float*)d_in[10];

    cudaFuncSetAttribute(lstm_wmma_kernel,
                         cudaFuncAttributeMaxDynamicSharedMemorySize, SMEM_BYTES);
    lstm_wmma_kernel<<<NB, NTHREADS, SMEM_BYTES>>>(
        x, w_ih0, w_hh0, b_ih0, b_hh0, w_ih1, w_hh1, b_ih1, b_hh1, w_fc, b_fc,
        (float*)d_out);
}